// round 11
// baseline (speedup 1.0000x reference)
#include <cuda_runtime.h>
#include <math.h>

#define NB    4       // batch / classes
#define DD    512     // feature dim
#define TPB   256
#define NCOMP 64      // compute blocks (8 output columns each)
#define NCOPY 528     // dedicated copy blocks (64+528 = 592 = 148 SMs x 4)
#define CPB   8
#define COMP_SHARE 6144   // float4 copied by each compute block (3 x 8-deep)
#define ALPHA_IT 0.7f
#define BETA_IT  0.5f

// Deep-batched streaming copy of [start, end) float4, block-stride TPB.
// Loads: plain (cached). Stores: evict-first streaming (__stcs) — the data is
// never re-read, so keep it out of the L2 working set.
__device__ __forceinline__ void copy_range(const float4* __restrict__ src,
                                           float4* __restrict__ dst,
                                           long long start, long long end,
                                           int tid)
{
    long long i = start + tid;
    #pragma unroll 1
    for (; i + 7 * TPB < end; i += 8 * TPB) {
        float4 a0 = src[i];
        float4 a1 = src[i + 1 * TPB];
        float4 a2 = src[i + 2 * TPB];
        float4 a3 = src[i + 3 * TPB];
        float4 a4 = src[i + 4 * TPB];
        float4 a5 = src[i + 5 * TPB];
        float4 a6 = src[i + 6 * TPB];
        float4 a7 = src[i + 7 * TPB];
        __stcs(dst + i,           a0);
        __stcs(dst + i + 1 * TPB, a1);
        __stcs(dst + i + 2 * TPB, a2);
        __stcs(dst + i + 3 * TPB, a3);
        __stcs(dst + i + 4 * TPB, a4);
        __stcs(dst + i + 5 * TPB, a5);
        __stcs(dst + i + 6 * TPB, a6);
        __stcs(dst + i + 7 * TPB, a7);
    }
    if (i + 3 * TPB < end) {
        float4 a0 = src[i];
        float4 a1 = src[i + 1 * TPB];
        float4 a2 = src[i + 2 * TPB];
        float4 a3 = src[i + 3 * TPB];
        __stcs(dst + i,           a0);
        __stcs(dst + i + 1 * TPB, a1);
        __stcs(dst + i + 2 * TPB, a2);
        __stcs(dst + i + 3 * TPB, a3);
        i += 4 * TPB;
    }
    if (i + TPB < end) {
        float4 a0 = src[i];
        float4 a1 = src[i + TPB];
        __stcs(dst + i,       a0);
        __stcs(dst + i + TPB, a1);
        i += 2 * TPB;
    }
    if (i < end)
        __stcs(dst + i, src[i]);
}

// Fused single kernel, load-balanced, exact single wave (592 blocks @ 4/SM):
//   blocks 0..63   : graph + dual GEMV -> refined, THEN copy COMP_SHARE f4
//   blocks 64..591 : stream their slice of img_feature -> out+2048
__global__ void __launch_bounds__(TPB, 4)
graphlearner_fused(const float* __restrict__ bt,    // (4,512)
                   const float* __restrict__ bi,    // (4,512)
                   const float* __restrict__ img,   // (40960,512)
                   const float* __restrict__ Wtt,   // (512,512)
                   const float* __restrict__ btt,   // (4,512)
                   const float* __restrict__ Wit,   // (512,512)
                   const float* __restrict__ bit_,  // (4,512)
                   float* __restrict__ out,
                   long long n_f4)
{
    const int tid = threadIdx.x;
    const float4* __restrict__ src = (const float4*)img;
    float4* __restrict__ dst = (float4*)(out + NB * DD);

    // copy-block share of the front region [0, base)
    const long long base = n_f4 - (long long)NCOMP * COMP_SHARE;
    const long long pshare = (base + NCOPY - 1) / NCOPY;

    // ---------------- dedicated copy blocks --------------------------------
    if (blockIdx.x >= NCOMP) {
        const long long start = (long long)(blockIdx.x - NCOMP) * pshare;
        long long end = start + pshare;
        if (end > base) end = base;
        copy_range(src, dst, start, end, tid);
        return;
    }

    // ---------------- compute blocks (verified R8/R9 path) -----------------
    const int warp = tid >> 5, lane = tid & 31;

    __shared__ float bt_s[NB][DD];                       // 8 KB
    __shared__ float bi_s[NB][DD];                       // 8 KB
    __shared__ __align__(16) float pacc_tt[64][32];      // 8 KB
    __shared__ __align__(16) float pacc_it[64][64];      // 16 KB
    __shared__ float raw[3][NB][NB];
    __shared__ float c_tt[NB][5], c_it[NB][5];
    __shared__ float sums[96];

    // ---- A: load features (float4) ----
    {
        const float4* bt4 = (const float4*)bt;
        const float4* bi4 = (const float4*)bi;
        #pragma unroll
        for (int i = tid; i < NB * DD / 4; i += TPB) {
            ((float4*)bt_s)[i] = bt4[i];
            ((float4*)bi_s)[i] = bi4[i];
        }
    }
    __syncthreads();

    // ---- B: per-node GEMV partials ----
    {
        const int g   = tid & 1;
        const int s   = (tid >> 1) & 63;
        const int mat = tid >> 7;
        const int d0  = blockIdx.x * CPB + g * 4;
        const float* __restrict__ W = mat ? Wit : Wtt;

        float4 accB[NB], accI[NB];
        #pragma unroll
        for (int m = 0; m < NB; m++) {
            accB[m] = make_float4(0.f, 0.f, 0.f, 0.f);
            accI[m] = make_float4(0.f, 0.f, 0.f, 0.f);
        }
        #pragma unroll
        for (int kk = 0; kk < 8; kk++) {
            const int k = kk * 64 + s;
            const float4 w = *(const float4*)(W + (size_t)k * DD + d0);
            #pragma unroll
            for (int m = 0; m < NB; m++) {
                const float bm = bt_s[m][k];
                accB[m].x = fmaf(bm, w.x, accB[m].x);
                accB[m].y = fmaf(bm, w.y, accB[m].y);
                accB[m].z = fmaf(bm, w.z, accB[m].z);
                accB[m].w = fmaf(bm, w.w, accB[m].w);
            }
            if (mat) {
                #pragma unroll
                for (int m = 0; m < NB; m++) {
                    const float im = bi_s[m][k];
                    accI[m].x = fmaf(im, w.x, accI[m].x);
                    accI[m].y = fmaf(im, w.y, accI[m].y);
                    accI[m].z = fmaf(im, w.z, accI[m].z);
                    accI[m].w = fmaf(im, w.w, accI[m].w);
                }
            }
        }
        if (mat == 0) {
            float4* row = (float4*)&pacc_tt[s][g * 16];
            #pragma unroll
            for (int m = 0; m < NB; m++) row[m] = accB[m];
        } else {
            float4* rowB = (float4*)&pacc_it[s][g * 16];
            float4* rowI = (float4*)&pacc_it[s][32 + g * 16];
            #pragma unroll
            for (int m = 0; m < NB; m++) { rowB[m] = accB[m]; rowI[m] = accI[m]; }
        }
    }

    // ---- C: gram dots, batched 4 per warp-pass ----
    {
        #pragma unroll
        for (int pass = 0; pass < 2; pass++) {
            if (pass == 1 && warp >= 4) break;
            const int G   = (pass == 0) ? warp : 8 + warp;
            const int mat = G >> 2, i = G & 3;
            const float4* a4 = (const float4*)((mat == 2) ? bi_s[i] : bt_s[i]);
            const float4* cb = (const float4*)((mat == 0) ? &bt_s[0][0]
                                                          : &bi_s[0][0]);
            float a0 = 0.f, a1 = 0.f, a2 = 0.f, a3 = 0.f;
            #pragma unroll
            for (int ch = 0; ch < 4; ch++) {
                const int o = lane + 32 * ch;
                const float4 av = a4[o];
                const float4 c0 = cb[0 * 128 + o];
                const float4 c1 = cb[1 * 128 + o];
                const float4 c2 = cb[2 * 128 + o];
                const float4 c3 = cb[3 * 128 + o];
                a0 = fmaf(av.x, c0.x, fmaf(av.y, c0.y, fmaf(av.z, c0.z, fmaf(av.w, c0.w, a0))));
                a1 = fmaf(av.x, c1.x, fmaf(av.y, c1.y, fmaf(av.z, c1.z, fmaf(av.w, c1.w, a1))));
                a2 = fmaf(av.x, c2.x, fmaf(av.y, c2.y, fmaf(av.z, c2.z, fmaf(av.w, c2.w, a2))));
                a3 = fmaf(av.x, c3.x, fmaf(av.y, c3.y, fmaf(av.z, c3.z, fmaf(av.w, c3.w, a3))));
            }
            #pragma unroll
            for (int off = 16; off > 0; off >>= 1) {
                a0 += __shfl_down_sync(0xffffffffu, a0, off);
                a1 += __shfl_down_sync(0xffffffffu, a1, off);
                a2 += __shfl_down_sync(0xffffffffu, a2, off);
                a3 += __shfl_down_sync(0xffffffffu, a3, off);
            }
            if (lane == 0) {
                raw[mat][i][0] = a0; raw[mat][i][1] = a1;
                raw[mat][i][2] = a2; raw[mat][i][3] = a3;
            }
        }
    }
    __syncthreads();

    // ---- D (parallel): split-reduction + tiny graph ----
    if (tid < 32) {
        float s0 = 0.f, s1 = 0.f, s2 = 0.f, s3 = 0.f;
        #pragma unroll
        for (int s = 0; s < 64; s += 4) {
            s0 += pacc_tt[s][tid];     s1 += pacc_tt[s + 1][tid];
            s2 += pacc_tt[s + 2][tid]; s3 += pacc_tt[s + 3][tid];
        }
        sums[tid] = (s0 + s1) + (s2 + s3);
    } else if (tid < 96) {
        const int idx = tid - 32;
        float s0 = 0.f, s1 = 0.f, s2 = 0.f, s3 = 0.f;
        #pragma unroll
        for (int s = 0; s < 64; s += 4) {
            s0 += pacc_it[s][idx];     s1 += pacc_it[s + 1][idx];
            s2 += pacc_it[s + 2][idx]; s3 += pacc_it[s + 3][idx];
        }
        sums[32 + idx] = (s0 + s1) + (s2 + s3);
    } else if (tid >= 224 && tid < 232) {
        const int b = tid & 3;
        const bool is_it = (tid & 4) != 0;
        float rnt[NB], rni[NB];
        #pragma unroll
        for (int i = 0; i < NB; i++) {
            rnt[i] = rsqrtf(fmaxf(raw[0][i][i], 1e-24f));
            rni[i] = rsqrtf(fmaxf(raw[2][i][i], 1e-24f));
        }
        float e[5][5];
        if (!is_it) {
            e[0][0] = raw[0][b][b] * rnt[b] * rnt[b];
            #pragma unroll
            for (int m = 1; m < 5; m++) {
                e[0][m] = raw[0][b][m - 1] * rnt[b] * rnt[m - 1];
                e[m][0] = raw[0][m - 1][b] * rnt[m - 1] * rnt[b];
            }
            #pragma unroll
            for (int n = 1; n < 5; n++)
                #pragma unroll
                for (int m = 1; m < 5; m++)
                    e[n][m] = raw[0][n - 1][m - 1] * rnt[n - 1] * rnt[m - 1];
        } else {
            e[0][0] = raw[0][b][b] * rnt[b] * rnt[b];
            #pragma unroll
            for (int m = 1; m < 5; m++) {
                e[0][m] = raw[1][b][m - 1] * rnt[b] * rni[m - 1];
                e[m][0] = e[0][m];
            }
            #pragma unroll
            for (int n = 1; n < 5; n++)
                #pragma unroll
                for (int m = 1; m < 5; m++)
                    e[n][m] = raw[2][n - 1][m - 1] * rni[n - 1] * rni[m - 1];
        }
        float adj[5][5], deg[5];
        #pragma unroll
        for (int n = 0; n < 5; n++) {
            deg[n] = 0.f;
            #pragma unroll
            for (int m = 0; m < 5; m++) {
                adj[n][m] = fmaxf(e[n][m], 0.f) + ((n == m) ? 1.f : 0.f);
                deg[n] += adj[n][m];
            }
        }
        float dinv[5];
        #pragma unroll
        for (int n = 0; n < 5; n++)
            dinv[n] = rsqrtf(deg[n]);
        float* cc = is_it ? c_it[b] : c_tt[b];
        #pragma unroll
        for (int m = 0; m < 5; m++)
            cc[m] = dinv[0] * adj[0][m] * dinv[m];
    }
    __syncthreads();

    // ---- E: combine + bias + tanh + blend (32 threads) ----
    if (tid < 32) {
        const int col = tid & 7;
        const int b   = tid >> 3;
        const int g   = col >> 2, c = col & 3;
        const int d   = blockIdx.x * CPB + col;
        const int o   = g * 16 + c;

        float att = c_tt[b][0] * sums[o + b * 4];
        float ait = c_it[b][0] * sums[32 + o + b * 4];
        #pragma unroll
        for (int j = 0; j < 4; j++) {
            att = fmaf(c_tt[b][j + 1], sums[o + j * 4],      att);
            ait = fmaf(c_it[b][j + 1], sums[64 + o + j * 4], ait);
        }
        const float stt = att + btt[b * DD + d];
        const float sit = ait + bit_[b * DD + d];
        const float gg = ALPHA_IT * tanhf(stt) + (1.f - ALPHA_IT) * tanhf(sit);
        out[b * DD + d] = BETA_IT * bt_s[b][d] + (1.f - BETA_IT) * gg;
    }

    // ---- F: join the copy — tail region [base, n_f4) ----
    {
        const long long start = base + (long long)blockIdx.x * COMP_SHARE;
        copy_range(src, dst, start, start + COMP_SHARE, tid);
    }
}

extern "C" void kernel_launch(void* const* d_in, const int* in_sizes, int n_in,
                              void* d_out, int out_size) {
    const float* bt   = (const float*)d_in[0];
    const float* bi   = (const float*)d_in[1];
    const float* img  = (const float*)d_in[2];
    const float* Wtt  = (const float*)d_in[3];
    const float* btt  = (const float*)d_in[4];
    const float* Wit  = (const float*)d_in[5];
    const float* bit_ = (const float*)d_in[6];
    float* out = (float*)d_out;

    const long long n_f4 = (long long)in_sizes[2] / 4;   // 5,242,880

    dim3 grid(NCOMP + NCOPY), block(TPB);   // 592 blocks = 148 SMs x 4, 1 wave
    graphlearner_fused<<<grid, block>>>(bt, bi, img, Wtt, btt, Wit, bit_,
                                        out, n_f4);
}